// round 11
// baseline (speedup 1.0000x reference)
#include <cuda_runtime.h>
#include <cuda_bf16.h>
#include <cstdint>
#include <math.h>

#define BB   32
#define SS   256
#define DD   768
#define HH   8
#define HDIM 96
#define NL   6
#define NQKV (3*DD)   // 2304

// ---------------- scratch (static device globals; no allocs allowed) ------
__device__ float g_x [BB*SS*DD];          // fp32 activation (layer in/out)
__device__ float g_of[BB*SS*DD];          // fp32 attention output
__device__ float g_bias[HH*SS*SS];
__device__ float g_w [SS*DD];
__device__ float g_pq[SS*DD];
__device__ float g_pk[SS*DD];

__device__ __nv_bfloat16 g_qkvh[(long)BB*SS*NQKV], g_qkvl[(long)BB*SS*NQKV];
__device__ __nv_bfloat16 g_ah[(long)BB*HH*SS*SS], g_al[(long)BB*HH*SS*SS];

// int8 limb buffers + row scales
__device__ char  g_x1[BB*SS*DD],  g_x0[BB*SS*DD];
__device__ char  g_o1[BB*SS*DD],  g_o0[BB*SS*DD];
__device__ float g_sx[BB*SS],     g_so[BB*SS];
__device__ char  g_w1[(long)NL*NQKV*DD], g_w0[(long)NL*NQKV*DD];
__device__ float g_swq[NL*NQKV];
__device__ char  g_wo1[(long)NL*DD*DD],  g_wo0[(long)NL*DD*DD];
__device__ float g_swo[NL*DD];
__device__ float g_bqkv[NL*NQKV];

// =====================  low-level helpers  =================================
__device__ __forceinline__ uint32_t smem_u32(const void* p) {
    uint32_t a;
    asm("{ .reg .u64 t; cvta.to.shared.u64 t, %1; cvt.u32.u64 %0, t; }" : "=r"(a) : "l"(p));
    return a;
}
__device__ __forceinline__ void cp16(uint32_t s, const void* g) {
    asm volatile("cp.async.cg.shared.global [%0], [%1], 16;" :: "r"(s), "l"(g));
}
__device__ __forceinline__ void cp16z(uint32_t s, const void* g, int ok) {
    int sz = ok ? 16 : 0;
    asm volatile("cp.async.cg.shared.global [%0], [%1], 16, %2;" :: "r"(s), "l"(g), "r"(sz));
}
__device__ __forceinline__ void cp_commit() { asm volatile("cp.async.commit_group;"); }

__device__ __forceinline__ void ldm4(uint32_t* r, uint32_t a) {
    asm volatile("ldmatrix.sync.aligned.m8n8.x4.shared.b16 {%0,%1,%2,%3}, [%4];"
        : "=r"(r[0]), "=r"(r[1]), "=r"(r[2]), "=r"(r[3]) : "r"(a));
}
__device__ __forceinline__ void ldm4t(uint32_t* r, uint32_t a) {
    asm volatile("ldmatrix.sync.aligned.m8n8.x4.trans.shared.b16 {%0,%1,%2,%3}, [%4];"
        : "=r"(r[0]), "=r"(r[1]), "=r"(r[2]), "=r"(r[3]) : "r"(a));
}
__device__ __forceinline__ void mma16816(float* d, const uint32_t* a, const uint32_t* b) {
    asm volatile(
        "mma.sync.aligned.m16n8k16.row.col.f32.bf16.bf16.f32 "
        "{%0,%1,%2,%3}, {%4,%5,%6,%7}, {%8,%9}, {%0,%1,%2,%3};"
        : "+f"(d[0]), "+f"(d[1]), "+f"(d[2]), "+f"(d[3])
        : "r"(a[0]), "r"(a[1]), "r"(a[2]), "r"(a[3]), "r"(b[0]), "r"(b[1]));
}
__device__ __forceinline__ void mma16832i(int* d, const uint32_t* a, const uint32_t* b) {
    asm volatile(
        "mma.sync.aligned.m16n8k32.row.col.s32.s8.s8.s32 "
        "{%0,%1,%2,%3}, {%4,%5,%6,%7}, {%8,%9}, {%0,%1,%2,%3};"
        : "+r"(d[0]), "+r"(d[1]), "+r"(d[2]), "+r"(d[3])
        : "r"(a[0]), "r"(a[1]), "r"(a[2]), "r"(a[3]), "r"(b[0]), "r"(b[1]));
}

// ---------------- block reductions ----------------------------------------
__device__ __forceinline__ float blockReduceSum(float v, float* red) {
    #pragma unroll
    for (int o = 16; o > 0; o >>= 1) v += __shfl_xor_sync(0xffffffffu, v, o);
    int w = threadIdx.x >> 5;
    if ((threadIdx.x & 31) == 0) red[w] = v;
    __syncthreads();
    if (threadIdx.x < 32) {
        float t = (threadIdx.x < (blockDim.x >> 5)) ? red[threadIdx.x] : 0.f;
        #pragma unroll
        for (int o = 16; o > 0; o >>= 1) t += __shfl_xor_sync(0xffffffffu, t, o);
        if (threadIdx.x == 0) red[0] = t;
    }
    __syncthreads();
    float r = red[0];
    __syncthreads();
    return r;
}
__device__ __forceinline__ float blockReduceMax(float v, float* red) {
    #pragma unroll
    for (int o = 16; o > 0; o >>= 1) v = fmaxf(v, __shfl_xor_sync(0xffffffffu, v, o));
    int w = threadIdx.x >> 5;
    if ((threadIdx.x & 31) == 0) red[w] = v;
    __syncthreads();
    if (threadIdx.x < 32) {
        float t = (threadIdx.x < (blockDim.x >> 5)) ? red[threadIdx.x] : 0.f;
        #pragma unroll
        for (int o = 16; o > 0; o >>= 1) t = fmaxf(t, __shfl_xor_sync(0xffffffffu, t, o));
        if (threadIdx.x == 0) red[0] = t;
    }
    __syncthreads();
    float r = red[0];
    __syncthreads();
    return r;
}

// =====================  int8 limb GEMM (BT=true only)  =====================
// C[m,n] = Sa[m]*Sb[n]*(P1*16384 + P2*128) + bias[n]
// where A = Sa*(A1*128+A0), B = Sb*(B1*128+B0); P1=A1@B1^T, P2=A1@B0^T+A0@B1^T.
// Tile 128x128, warps 2m x 4n (warp 64x32), BK=128 int8, 3 stages dist-2.
// stage: A1 0 (16KB), A0 16384, B1 32768, B0 49152
#define GI_STAGE 65536
#define GI_SMEM  (3*GI_STAGE)   // 196608

__global__ void __launch_bounds__(256, 1)
gemm_i8(const char* __restrict__ A1, const char* __restrict__ A0, int lda,
        const float* __restrict__ Sa,
        const char* __restrict__ B1, const char* __restrict__ B0, int ldb,
        const float* __restrict__ Sb,
        float* __restrict__ Cf, __nv_bfloat16* __restrict__ Ch, __nv_bfloat16* __restrict__ Cl,
        int ldc, const float* __restrict__ bias, int K)
{
    extern __shared__ char smem[];
    const uint32_t sb = smem_u32(smem);
    const int m0 = blockIdx.y * 128;
    const int n0 = blockIdx.x * 128;
    const int tid = threadIdx.x, lane = tid & 31, wid = tid >> 5;
    const int wm = wid & 1, wn = wid >> 1;

    const char* gA1 = A1 + (long)m0 * lda;
    const char* gA0 = A0 + (long)m0 * lda;
    const char* gB1 = B1 + (long)n0 * ldb;
    const char* gB0 = B0 + (long)n0 * ldb;

    int p1[4][4][4] = {};
    int p2[4][4][4] = {};

    auto loads = [&](int kb, int st) {
        uint32_t s = sb + st * GI_STAGE;
        long ko = (long)kb * 128;
        #pragma unroll
        for (int e = 0; e < 4; e++) {
            int idx = tid + e * 256;          // 1024 chunks: 128 rows x 8x16B
            int r = idx >> 3, c = idx & 7;
            int cs = c ^ (r & 7);
            cp16(s +         r * 128 + cs * 16, gA1 + (long)r * lda + ko + c * 16);
            cp16(s + 16384 + r * 128 + cs * 16, gA0 + (long)r * lda + ko + c * 16);
        }
        #pragma unroll
        for (int e = 0; e < 4; e++) {
            int idx = tid + e * 256;
            int r = idx >> 3, c = idx & 7;
            int cs = c ^ (r & 7);
            cp16(s + 32768 + r * 128 + cs * 16, gB1 + (long)r * ldb + ko + c * 16);
            cp16(s + 49152 + r * 128 + cs * 16, gB0 + (long)r * ldb + ko + c * 16);
        }
        cp_commit();
    };

    auto comp = [&](int st) {
        uint32_t s = sb + st * GI_STAGE;
        #pragma unroll
        for (int kk = 0; kk < 4; kk++) {      // 4 x k32 (32 bytes each)
            uint32_t a1[4][4], a0[4][4], b1[4][2], b0[4][2];
            #pragma unroll
            for (int mf = 0; mf < 4; mf++) {
                int r = wm * 64 + mf * 16 + (lane & 15);
                int c = kk * 2 + (lane >> 4);
                int cs = c ^ (r & 7);
                ldm4(a1[mf], s +         r * 128 + cs * 16);
                ldm4(a0[mf], s + 16384 + r * 128 + cs * 16);
            }
            #pragma unroll
            for (int np = 0; np < 2; np++) {
                int r = wn * 32 + np * 16 + (lane & 7) + ((lane >> 4) & 1) * 8;
                int c = kk * 2 + ((lane >> 3) & 1);
                int cs = c ^ (r & 7);
                uint32_t t[4];
                ldm4(t, s + 32768 + r * 128 + cs * 16);
                b1[2*np][0]=t[0]; b1[2*np][1]=t[1]; b1[2*np+1][0]=t[2]; b1[2*np+1][1]=t[3];
                ldm4(t, s + 49152 + r * 128 + cs * 16);
                b0[2*np][0]=t[0]; b0[2*np][1]=t[1]; b0[2*np+1][0]=t[2]; b0[2*np+1][1]=t[3];
            }
            #pragma unroll
            for (int mf = 0; mf < 4; mf++)
                #pragma unroll
                for (int nf = 0; nf < 4; nf++) {
                    mma16832i(p1[mf][nf], a1[mf], b1[nf]);
                    mma16832i(p2[mf][nf], a1[mf], b0[nf]);
                    mma16832i(p2[mf][nf], a0[mf], b1[nf]);
                }
        }
    };

    const int nkb = K / 128;                 // 6 (K=768)
    loads(0, 0);
    loads(1, 1);
    for (int kb = 0; kb < nkb; kb++) {
        if (kb + 1 < nkb) asm volatile("cp.async.wait_group 1;");
        else              asm volatile("cp.async.wait_group 0;");
        __syncthreads();
        if (kb + 2 < nkb) loads(kb + 2, (kb + 2) % 3);
        comp(kb % 3);
    }

    // ---- epilogue: combine limbs with scales ----
    #pragma unroll
    for (int mf = 0; mf < 4; mf++) {
        int rbase = m0 + wm * 64 + mf * 16 + (lane >> 2);
        float saA = Sa[rbase];
        float saB = Sa[rbase + 8];
        #pragma unroll
        for (int nf = 0; nf < 4; nf++) {
            int col = n0 + wn * 32 + nf * 8 + (lane & 3) * 2;
            float sb0 = Sb[col], sb1 = Sb[col + 1];
            float bv0 = bias[col], bv1 = bias[col + 1];
            #pragma unroll
            for (int h = 0; h < 2; h++) {
                int rr = rbase + h * 8;
                float sa = h ? saB : saA;
                float v0 = sa * sb0 * ((float)p1[mf][nf][h*2+0] * 16384.f
                                     + (float)p2[mf][nf][h*2+0] * 128.f) + bv0;
                float v1 = sa * sb1 * ((float)p1[mf][nf][h*2+1] * 16384.f
                                     + (float)p2[mf][nf][h*2+1] * 128.f) + bv1;
                long i0 = (long)rr * ldc + col;
                if (Cf) { Cf[i0] = v0; Cf[i0 + 1] = v1; }
                if (Ch) {
                    __nv_bfloat16 h0 = __float2bfloat16(v0);
                    __nv_bfloat16 h1 = __float2bfloat16(v1);
                    *(__nv_bfloat162*)(Ch + i0) = __nv_bfloat162(h0, h1);
                    *(__nv_bfloat162*)(Cl + i0) = __nv_bfloat162(
                        __float2bfloat16(v0 - __bfloat162float(h0)),
                        __float2bfloat16(v1 - __bfloat162float(h1)));
                }
            }
        }
    }
}

// ============== per-row activation quantization (768 cols) =================
__global__ void qact_k(const float* __restrict__ src, char* __restrict__ q1,
                       char* __restrict__ q0, float* __restrict__ sc)
{
    __shared__ float red[32];
    int row = blockIdx.x;
    const float* xr = src + (long)row * DD;
    int tid = threadIdx.x;
    float v[3];
    float m = 0.f;
    #pragma unroll
    for (int e = 0; e < 3; e++) { v[e] = xr[tid + e * 256]; m = fmaxf(m, fabsf(v[e])); }
    m = blockReduceMax(m, red);
    float inv = (m > 0.f) ? 16256.f / m : 0.f;
    if (tid == 0) sc[row] = (m > 0.f) ? m / 16256.f : 1.f;
    #pragma unroll
    for (int e = 0; e < 3; e++) {
        int c = tid + e * 256;
        int i = __float2int_rn(v[e] * inv);
        int a1 = __float2int_rn((float)i * 0.0078125f);   // /128 round-nearest
        int a0 = i - (a1 << 7);
        q1[(long)row * DD + c] = (char)a1;
        q0[(long)row * DD + c] = (char)a0;
    }
}

// ============ weight quantization: QKV combined [NL*2304 rows x 768] =======
__global__ void packqkv_i8(const float* __restrict__ Wq, const float* __restrict__ Wk,
                           const float* __restrict__ Wv, float scale)
{
    __shared__ float red[32];
    int gr = blockIdx.x;                 // l*NQKV + row
    int l = gr / NQKV, row = gr % NQKV;
    const float* src; float fs = 1.f; int r = row;
    if (row < DD)        { src = Wq; fs = scale; }
    else if (row < 2*DD) { src = Wk; r = row - DD; }
    else                 { src = Wv; r = row - 2*DD; }
    const float* xr = src + ((long)l * DD + r) * DD;
    int tid = threadIdx.x;
    float v[3];
    float m = 0.f;
    #pragma unroll
    for (int e = 0; e < 3; e++) { v[e] = xr[tid + e * 256] * fs; m = fmaxf(m, fabsf(v[e])); }
    m = blockReduceMax(m, red);
    float inv = (m > 0.f) ? 16256.f / m : 0.f;
    if (tid == 0) g_swq[gr] = (m > 0.f) ? m / 16256.f : 1.f;
    #pragma unroll
    for (int e = 0; e < 3; e++) {
        int c = tid + e * 256;
        int i = __float2int_rn(v[e] * inv);
        int a1 = __float2int_rn((float)i * 0.0078125f);
        int a0 = i - (a1 << 7);
        g_w1[(long)gr * DD + c] = (char)a1;
        g_w0[(long)gr * DD + c] = (char)a0;
    }
}

__global__ void packwo_i8(const float* __restrict__ Wo)
{
    __shared__ float red[32];
    int gr = blockIdx.x;                 // l*DD + row
    const float* xr = Wo + (long)gr * DD;
    int tid = threadIdx.x;
    float v[3];
    float m = 0.f;
    #pragma unroll
    for (int e = 0; e < 3; e++) { v[e] = xr[tid + e * 256]; m = fmaxf(m, fabsf(v[e])); }
    m = blockReduceMax(m, red);
    float inv = (m > 0.f) ? 16256.f / m : 0.f;
    if (tid == 0) g_swo[gr] = (m > 0.f) ? m / 16256.f : 1.f;
    #pragma unroll
    for (int e = 0; e < 3; e++) {
        int c = tid + e * 256;
        int i = __float2int_rn(v[e] * inv);
        int a1 = __float2int_rn((float)i * 0.0078125f);
        int a0 = i - (a1 << 7);
        g_wo1[(long)gr * DD + c] = (char)a1;
        g_wo0[(long)gr * DD + c] = (char)a0;
    }
}

__global__ void packbias_k(const float* __restrict__ bq, const float* __restrict__ bk,
                           const float* __restrict__ bv, float scale)
{
    int idx = blockIdx.x * blockDim.x + threadIdx.x;
    if (idx >= NL * NQKV) return;
    int row = idx % NQKV, l = idx / NQKV;
    float v;
    if (row < DD)        v = bq[l*DD + row] * scale;
    else if (row < 2*DD) v = bk[l*DD + row - DD];
    else                 v = bv[l*DD + row - 2*DD];
    g_bqkv[idx] = v;
}

// =====================  bf16 split GEMM (attn@v only)  =====================
// CTA tile 256x128, warp 64x64 (4m x 2n), BK=64, 2-stage, BT=false.
#define GM_STAGE  98304
#define GM_SMEM   (2*GM_STAGE)   // 196608

__global__ void __launch_bounds__(256, 1)
gemm_bf(const __nv_bfloat16* __restrict__ Ah, const __nv_bfloat16* __restrict__ Al,
        int lda, long aO, long aI,
        const __nv_bfloat16* __restrict__ Bh, const __nv_bfloat16* __restrict__ Bl,
        int ldb, long bO, long bI,
        float* __restrict__ Cf, int ldc, long cO, long cI,
        int N, int K, int batchInner)
{
    extern __shared__ char smem[];
    const uint32_t sb = smem_u32(smem);
    const int z  = blockIdx.z;
    const long zo = z / batchInner, zi = z % batchInner;
    Ah += zo * aO + zi * aI;  Al += zo * aO + zi * aI;
    Bh += zo * bO + zi * bI;  Bl += zo * bO + zi * bI;
    const long coff = zo * cO + zi * cI;

    const int m0 = blockIdx.y * 256;
    const int n0 = blockIdx.x * 128;
    const int tid = threadIdx.x, lane = tid & 31, wid = tid >> 5;
    const int wm = wid & 3, wn = wid >> 2;

    const __nv_bfloat16* gAh = Ah + (long)m0 * lda;
    const __nv_bfloat16* gAl = Al + (long)m0 * lda;
    const __nv_bfloat16* gBh = Bh + n0;
    const __nv_bfloat16* gBl = Bl + n0;

    float acc[4][8][4] = {};

    auto loads = [&](int kb, int st) {
        uint32_t s = sb + st * GM_STAGE;
        long ko = (long)kb * 64;
        #pragma unroll
        for (int e = 0; e < 8; e++) {
            int idx = tid + e * 256;
            int r = idx >> 3, c = idx & 7;
            int cs = c ^ (r & 7);
            cp16(s +         r * 128 + cs * 16, gAh + (long)r * lda + ko + c * 8);
            cp16(s + 32768 + r * 128 + cs * 16, gAl + (long)r * lda + ko + c * 8);
        }
        #pragma unroll
        for (int e = 0; e < 4; e++) {
            int idx = tid + e * 256;
            int r = idx >> 4, c = idx & 15;
            int cs = c ^ (r & 7);
            int ok = (n0 + c * 8) < N;
            int co = ok ? c * 8 : 0;
            cp16z(s + 65536 + r * 256 + cs * 16, gBh + (ko + r) * (long)ldb + co, ok);
            cp16z(s + 81920 + r * 256 + cs * 16, gBl + (ko + r) * (long)ldb + co, ok);
        }
        cp_commit();
    };

    auto comp = [&](int st) {
        uint32_t s = sb + st * GM_STAGE;
        #pragma unroll
        for (int kk = 0; kk < 4; kk++) {
            uint32_t ah[4][4], al[4][4], bh[8][2], bl[8][2];
            #pragma unroll
            for (int mf = 0; mf < 4; mf++) {
                int r = wm * 64 + mf * 16 + (lane & 15);
                int c = kk * 2 + (lane >> 4);
                int cs = c ^ (r & 7);
                ldm4(ah[mf], s +         r * 128 + cs * 16);
                ldm4(al[mf], s + 32768 + r * 128 + cs * 16);
            }
            #pragma unroll
            for (int np = 0; np < 4; np++) {
                int kr = kk * 16 + (lane & 15);
                int nc = (wn * 64 + np * 16) / 8 + ((lane >> 4) & 1);
                int cs = nc ^ (kr & 7);
                uint32_t t[4];
                ldm4t(t, s + 65536 + kr * 256 + cs * 16);
                bh[2*np][0]=t[0]; bh[2*np][1]=t[1]; bh[2*np+1][0]=t[2]; bh[2*np+1][1]=t[3];
                ldm4t(t, s + 81920 + kr * 256 + cs * 16);
                bl[2*np][0]=t[0]; bl[2*np][1]=t[1]; bl[2*np+1][0]=t[2]; bl[2*np+1][1]=t[3];
            }
            #pragma unroll
            for (int mf = 0; mf < 4; mf++)
                #pragma unroll
                for (int nf = 0; nf < 8; nf++) {
                    mma16816(acc[mf][nf], ah[mf], bh[nf]);
                    mma16816(acc[mf][nf], ah[mf], bl[nf]);
                    mma16816(acc[mf][nf], al[mf], bh[nf]);
                }
        }
    };

    const int nkb = K / 64;
    loads(0, 0);
    for (int kb = 0; kb < nkb; kb++) {
        asm volatile("cp.async.wait_group 0;");
        __syncthreads();
        if (kb + 1 < nkb) loads(kb + 1, (kb + 1) & 1);
        comp(kb & 1);
    }

    #pragma unroll
    for (int mf = 0; mf < 4; mf++) {
        int rbase = m0 + wm * 64 + mf * 16 + (lane >> 2);
        #pragma unroll
        for (int nf = 0; nf < 8; nf++) {
            int col = n0 + wn * 64 + nf * 8 + (lane & 3) * 2;
            if (col >= N) continue;
            #pragma unroll
            for (int h = 0; h < 2; h++) {
                int rr = rbase + h * 8;
                long i0 = coff + (long)rr * ldc + col;
                Cf[i0]     = acc[mf][nf][h * 2 + 0];
                Cf[i0 + 1] = acc[mf][nf][h * 2 + 1];
            }
        }
    }
}

// ========== fused scores + bias + softmax (emits attn hi/lo bf16) ==========
#define AT_STAGE 49152
#define AT_SMEM  (3*AT_STAGE)   // 147456

__global__ void __launch_bounds__(256, 1)
attn_sm_k(const __nv_bfloat16* __restrict__ Qh, const __nv_bfloat16* __restrict__ Ql,
          const __nv_bfloat16* __restrict__ Kh, const __nv_bfloat16* __restrict__ Kl,
          __nv_bfloat16* __restrict__ Ph, __nv_bfloat16* __restrict__ Pl)
{
    extern __shared__ char smem[];
    __shared__ float s_red[128][8];
    const uint32_t sb = smem_u32(smem);
    const int z = blockIdx.y;
    const int b = z / HH, h = z % HH;
    const int m0 = blockIdx.x * 128;
    const int tid = threadIdx.x, lane = tid & 31, w = tid >> 5;

    const long off = (long)b * SS * NQKV + (long)h * HDIM;
    const __nv_bfloat16* gQh = Qh + off + (long)m0 * NQKV;
    const __nv_bfloat16* gQl = Ql + off + (long)m0 * NQKV;
    const __nv_bfloat16* gKh = Kh + off;
    const __nv_bfloat16* gKl = Kl + off;

    float acc[8][4][4] = {};

    auto loads = [&](int kb) {
        uint32_t s = sb + kb * AT_STAGE;
        long ko = (long)kb * 32;
        #pragma unroll
        for (int e = 0; e < 2; e++) {
            int idx = tid + e * 256;
            int r = idx >> 2, c = idx & 3;
            int cs = c ^ ((r >> 1) & 3);
            cp16(s +        r * 64 + cs * 16, gQh + (long)r * NQKV + ko + c * 8);
            cp16(s + 8192 + r * 64 + cs * 16, gQl + (long)r * NQKV + ko + c * 8);
        }
        #pragma unroll
        for (int e = 0; e < 4; e++) {
            int idx = tid + e * 256;
            int r = idx >> 2, c = idx & 3;
            int cs = c ^ ((r >> 1) & 3);
            cp16(s + 16384 + r * 64 + cs * 16, gKh + (long)r * NQKV + ko + c * 8);
            cp16(s + 32768 + r * 64 + cs * 16, gKl + (long)r * NQKV + ko + c * 8);
        }
        cp_commit();
    };

    loads(0); loads(1);
    for (int kb = 0; kb < 3; kb++) {
        if (kb < 2) asm volatile("cp.async.wait_group 1;");
        else        asm volatile("cp.async.wait_group 0;");
        __syncthreads();
        if (kb + 2 < 3) loads(kb + 2);
        uint32_t s = sb + kb * AT_STAGE;
        #pragma unroll
        for (int kk = 0; kk < 2; kk++) {
            uint32_t bh[4][2], bl[4][2];
            #pragma unroll
            for (int np = 0; np < 2; np++) {
                int r = w * 32 + np * 16 + (lane & 7) + ((lane >> 4) & 1) * 8;
                int c = kk * 2 + ((lane >> 3) & 1);
                int cs = c ^ ((r >> 1) & 3);
                uint32_t t[4];
                ldm4(t, s + 16384 + r * 64 + cs * 16);
                bh[2*np][0]=t[0]; bh[2*np][1]=t[1]; bh[2*np+1][0]=t[2]; bh[2*np+1][1]=t[3];
                ldm4(t, s + 32768 + r * 64 + cs * 16);
                bl[2*np][0]=t[0]; bl[2*np][1]=t[1]; bl[2*np+1][0]=t[2]; bl[2*np+1][1]=t[3];
            }
            #pragma unroll
            for (int half = 0; half < 2; half++) {
                uint32_t ah[4][4], al[4][4];
                #pragma unroll
                for (int mq = 0; mq < 4; mq++) {
                    int mf = half * 4 + mq;
                    int r = mf * 16 + (lane & 15);
                    int c = kk * 2 + (lane >> 4);
                    int cs = c ^ ((r >> 1) & 3);
                    ldm4(ah[mq], s +        r * 64 + cs * 16);
                    ldm4(al[mq], s + 8192 + r * 64 + cs * 16);
                }
                #pragma unroll
                for (int mq = 0; mq < 4; mq++)
                    #pragma unroll
                    for (int nf = 0; nf < 4; nf++) {
                        mma16816(acc[half*4+mq][nf], ah[mq], bh[nf]);
                        mma16816(acc[half*4+mq][nf], ah[mq], bl[nf]);
                        mma16816(acc[half*4+mq][nf], al[mq], bh[nf]);
                    }
            }
        }
    }

    const float* bp = g_bias + (long)h * SS * SS;
    #pragma unroll
    for (int mf = 0; mf < 8; mf++)
        #pragma unroll
        for (int sub = 0; sub < 2; sub++) {
            int row = m0 + mf * 16 + (lane >> 2) + sub * 8;
            #pragma unroll
            for (int nf = 0; nf < 4; nf++) {
                int col = w * 32 + nf * 8 + (lane & 3) * 2;
                float2 bv = *(const float2*)(bp + (long)row * SS + col);
                acc[mf][nf][sub*2+0] += bv.x;
                acc[mf][nf][sub*2+1] += bv.y;
            }
        }

    float mx[8][2];
    #pragma unroll
    for (int mf = 0; mf < 8; mf++)
        #pragma unroll
        for (int sub = 0; sub < 2; sub++) {
            float m = -3.4e38f;
            #pragma unroll
            for (int nf = 0; nf < 4; nf++)
                m = fmaxf(m, fmaxf(acc[mf][nf][sub*2], acc[mf][nf][sub*2+1]));
            m = fmaxf(m, __shfl_xor_sync(0xffffffffu, m, 1));
            m = fmaxf(m, __shfl_xor_sync(0xffffffffu, m, 2));
            if ((lane & 3) == 0) s_red[mf*16 + (lane>>2) + sub*8][w] = m;
        }
    __syncthreads();
    #pragma unroll
    for (int mf = 0; mf < 8; mf++)
        #pragma unroll
        for (int sub = 0; sub < 2; sub++) {
            int r = mf*16 + (lane>>2) + sub*8;
            float m = s_red[r][0];
            #pragma unroll
            for (int ww = 1; ww < 8; ww++) m = fmaxf(m, s_red[r][ww]);
            mx[mf][sub] = m;
        }
    __syncthreads();

    float sm[8][2];
    #pragma unroll
    for (int mf = 0; mf < 8; mf++)
        #pragma unroll
        for (int sub = 0; sub < 2; sub++) {
            float ssum = 0.f;
            #pragma unroll
            for (int nf = 0; nf < 4; nf++) {
                float e0 = __expf(acc[mf][nf][sub*2+0] - mx[mf][sub]);
                float e1 = __expf(acc[mf][nf][sub*2+1] - mx[mf][sub]);
                acc[mf][nf][sub*2+0] = e0;
                acc[mf][nf][sub*2+1] = e1;
                ssum += e0 + e1;
            }
            ssum += __shfl_xor_sync(0xffffffffu, ssum, 1);
            ssum += __shfl_xor_sync(0xffffffffu, ssum, 2);
            if ((lane & 3) == 0) s_red[mf*16 + (lane>>2) + sub*8][w] = ssum;
        }
    __syncthreads();
    #pragma unroll
    for (int mf = 0; mf < 8; mf++)
        #pragma unroll
        for (int sub = 0; sub < 2; sub++) {
            int r = mf*16 + (lane>>2) + sub*8;
            float ssum = 0.f;
            #pragma unroll
            for (int ww = 0; ww < 8; ww++) ssum += s_red[r][ww];
            sm[mf][sub] = 1.f / ssum;
        }

    #pragma unroll
    for (int mf = 0; mf < 8; mf++)
        #pragma unroll
        for (int sub = 0; sub < 2; sub++) {
            int row = m0 + mf * 16 + (lane >> 2) + sub * 8;
            float r = sm[mf][sub];
            #pragma unroll
            for (int nf = 0; nf < 4; nf++) {
                int col = w * 32 + nf * 8 + (lane & 3) * 2;
                float p0 = acc[mf][nf][sub*2+0] * r;
                float p1 = acc[mf][nf][sub*2+1] * r;
                __nv_bfloat16 h0 = __float2bfloat16(p0);
                __nv_bfloat16 h1 = __float2bfloat16(p1);
                long idx = ((long)z * SS + row) * SS + col;
                *(__nv_bfloat162*)(Ph + idx) = __nv_bfloat162(h0, h1);
                *(__nv_bfloat162*)(Pl + idx) = __nv_bfloat162(
                    __float2bfloat16(p0 - __bfloat162float(h0)),
                    __float2bfloat16(p1 - __bfloat162float(h1)));
            }
        }
}

// ---------------- fp32 SGEMM (tiny positional-bias path only) -------------
template<bool BT, bool ACCUM>
__global__ void __launch_bounds__(256)
gemm_k(const float* __restrict__ A, int lda, long aO, long aI,
       const float* __restrict__ B, int ldb, long bO, long bI,
       float* __restrict__ C, int ldc, long cO, long cI,
       int M, int N, int K, int batchInner,
       float alpha, const float* __restrict__ biasVec)
{
    __shared__ float As[16][65];
    __shared__ float Bs[16][65];
    int z = blockIdx.z;
    A += (long)(z / batchInner) * aO + (long)(z % batchInner) * aI;
    B += (long)(z / batchInner) * bO + (long)(z % batchInner) * bI;
    C += (long)(z / batchInner) * cO + (long)(z % batchInner) * cI;
    const int m0 = blockIdx.y * 64, n0 = blockIdx.x * 64;
    const int tid = threadIdx.x, tx = tid & 15, ty = tid >> 4;
    float acc[4][4] = {};
    for (int k0 = 0; k0 < K; k0 += 16) {
        #pragma unroll
        for (int e = 0; e < 4; e++) {
            int i = tid + e * 256;
            int m = i >> 4, kk = i & 15;
            float val = 0.f;
            if (m0 + m < M && k0 + kk < K) val = A[(long)(m0 + m) * lda + (k0 + kk)];
            As[kk][m] = val;
        }
        #pragma unroll
        for (int e = 0; e < 4; e++) {
            int i = tid + e * 256;
            float val = 0.f;
            if (BT) {
                int n = i >> 4, kk = i & 15;
                if (n0 + n < N && k0 + kk < K) val = B[(long)(n0 + n) * ldb + (k0 + kk)];
                Bs[kk][n] = val;
            } else {
                int kk = i >> 6, n = i & 63;
                if (n0 + n < N && k0 + kk < K) val = B[(long)(k0 + kk) * ldb + (n0 + n)];
                Bs[kk][n] = val;
            }
        }
        __syncthreads();
        #pragma unroll
        for (int kk = 0; kk < 16; kk++) {
            float ra[4], rb[4];
            #pragma unroll
            for (int i = 0; i < 4; i++) ra[i] = As[kk][ty * 4 + i];
            #pragma unroll
            for (int j = 0; j < 4; j++) rb[j] = Bs[kk][tx * 4 + j];
            #pragma unroll
            for (int i = 0; i < 4; i++)
                #pragma unroll
                for (int j = 0; j < 4; j++)
                    acc[i][j] = fmaf(ra[i], rb[j], acc[i][j]);
        }
        __syncthreads();
    }
    #pragma unroll
    for (int i = 0; i < 4; i++) {
        int m = m0 + ty * 4 + i;
        if (m >= M) continue;
        #pragma unroll
        for (int j = 0; j < 4; j++) {
            int n = n0 + tx * 4 + j;
            if (n >= N) continue;
            float v = acc[i][j];
            if (biasVec) v += biasVec[n];
            v *= alpha;
            long idx = (long)m * ldc + n;
            if (ACCUM) C[idx] += v; else C[idx] = v;
        }
    }
}

// ---------------- layernorm of pos_emb rows -------------------------------
__global__ void ln_k(const float* __restrict__ x, const float* __restrict__ g,
                     const float* __restrict__ b)
{
    __shared__ float red[32];
    int row = blockIdx.x;
    const float* xr = x + (long)row * DD;
    int tid = threadIdx.x;
    float v[3];
    float s = 0.f;
    #pragma unroll
    for (int e = 0; e < 3; e++) { v[e] = xr[tid + e * 256]; s += v[e]; }
    float mu = blockReduceSum(s, red) * (1.0f / DD);
    float s2 = 0.f;
    #pragma unroll
    for (int e = 0; e < 3; e++) { float d = v[e] - mu; s2 += d * d; }
    float var = blockReduceSum(s2, red) * (1.0f / DD);
    float inv = rsqrtf(var + 1e-5f);
    #pragma unroll
    for (int e = 0; e < 3; e++) {
        int c = tid + e * 256;
        g_w[(long)row * DD + c] = (v[e] - mu) * inv * g[c] + b[c];
    }
}

// ---------------- relative bias init ---------------------------------------
__global__ void relbias_k(const float* __restrict__ table, const int* __restrict__ bucket)
{
    long idx = (long)blockIdx.x * blockDim.x + threadIdx.x;
    if (idx >= (long)HH * SS * SS) return;
    int j = idx % SS;
    long t = idx / SS;
    int i = t % SS;
    int h = t / SS;
    g_bias[idx] = table[bucket[i * SS + j] * HH + h];
}

// ---------------- embedding gather (fp32) ----------------------------------
__global__ void gather_k(const int* __restrict__ tok, const float* __restrict__ emb)
{
    long idx = (long)blockIdx.x * blockDim.x + threadIdx.x;
    if (idx >= (long)BB * SS * DD) return;
    int d = idx % DD;
    long bs = idx / DD;
    g_x[idx] = emb[(long)tok[bs] * DD + d];
}

// ---------------- final extraction ------------------------------------------
__global__ void extract_k(float* __restrict__ out)
{
    int idx = blockIdx.x * blockDim.x + threadIdx.x;
    if (idx >= BB * DD) return;
    int b = idx / DD, d = idx % DD;
    out[idx] = g_x[(long)b * SS * DD + d];
}

// ---------------------------------------------------------------------------
extern "C" void kernel_launch(void* const* d_in, const int* in_sizes, int n_in,
                              void* d_out, int out_size)
{
    const int*   tokens    = (const int*)  d_in[0];
    const float* embed     = (const float*)d_in[1];
    const float* pos_emb   = (const float*)d_in[2];
    const float* pos_q_w   = (const float*)d_in[3];
    const float* pos_q_b   = (const float*)d_in[4];
    const float* pos_k_w   = (const float*)d_in[5];
    const float* pos_k_b   = (const float*)d_in[6];
    const float* pos_ln_g  = (const float*)d_in[7];
    const float* pos_ln_b  = (const float*)d_in[8];
    const float* rel_table = (const float*)d_in[9];
    const int*   rp_bucket = (const int*)  d_in[10];
    const float* Wq = (const float*)d_in[11];
    const float* bq = (const float*)d_in[12];
    const float* Wk = (const float*)d_in[13];
    const float* bk = (const float*)d_in[14];
    const float* Wv = (const float*)d_in[15];
    const float* bv = (const float*)d_in[16];
    const float* Wo = (const float*)d_in[17];
    const float* bo = (const float*)d_in[18];
    float* out = (float*)d_out;

    float *px, *pof, *pbias, *pw, *ppq, *ppk, *pbqkv, *psx, *pso, *pswq, *pswo;
    cudaGetSymbolAddress((void**)&px,   g_x);
    cudaGetSymbolAddress((void**)&pof,  g_of);
    cudaGetSymbolAddress((void**)&pbias,g_bias);
    cudaGetSymbolAddress((void**)&pw,   g_w);
    cudaGetSymbolAddress((void**)&ppq,  g_pq);
    cudaGetSymbolAddress((void**)&ppk,  g_pk);
    cudaGetSymbolAddress((void**)&pbqkv,g_bqkv);
    cudaGetSymbolAddress((void**)&psx,  g_sx);
    cudaGetSymbolAddress((void**)&pso,  g_so);
    cudaGetSymbolAddress((void**)&pswq, g_swq);
    cudaGetSymbolAddress((void**)&pswo, g_swo);

    __nv_bfloat16 *pqkvh,*pqkvl,*pah,*pal;
    cudaGetSymbolAddress((void**)&pqkvh, g_qkvh); cudaGetSymbolAddress((void**)&pqkvl, g_qkvl);
    cudaGetSymbolAddress((void**)&pah, g_ah);     cudaGetSymbolAddress((void**)&pal, g_al);

    char *px1,*px0,*po1,*po0,*pw1,*pw0,*pwo1,*pwo0;
    cudaGetSymbolAddress((void**)&px1, g_x1);   cudaGetSymbolAddress((void**)&px0, g_x0);
    cudaGetSymbolAddress((void**)&po1, g_o1);   cudaGetSymbolAddress((void**)&po0, g_o0);
    cudaGetSymbolAddress((void**)&pw1, g_w1);   cudaGetSymbolAddress((void**)&pw0, g_w0);
    cudaGetSymbolAddress((void**)&pwo1, g_wo1); cudaGetSymbolAddress((void**)&pwo0, g_wo0);

    cudaFuncSetAttribute(gemm_i8, cudaFuncAttributeMaxDynamicSharedMemorySize, GI_SMEM);
    cudaFuncSetAttribute(gemm_bf, cudaFuncAttributeMaxDynamicSharedMemorySize, GM_SMEM);
    cudaFuncSetAttribute(attn_sm_k, cudaFuncAttributeMaxDynamicSharedMemorySize, AT_SMEM);

    const float scale = rsqrtf((float)(HDIM * 2));

    // ---- weight quantization (once) ----
    packqkv_i8<<<NL*NQKV, 256>>>(Wq, Wk, Wv, scale);
    packwo_i8<<<NL*DD, 256>>>(Wo);
    packbias_k<<<(NL*NQKV + 255)/256, 256>>>(bq, bk, bv, scale);

    // ---- positional bias (once; fp32 path) ----
    ln_k<<<SS, 256>>>(pos_emb, pos_ln_g, pos_ln_b);
    gemm_k<true,false><<<dim3(12,4,1),256>>>(pw,DD,0,0, pos_q_w,DD,0,0, ppq,DD,0,0,
                                             SS,DD,DD, 1, scale, pos_q_b);
    gemm_k<true,false><<<dim3(12,4,1),256>>>(pw,DD,0,0, pos_k_w,DD,0,0, ppk,DD,0,0,
                                             SS,DD,DD, 1, 1.0f, pos_k_b);
    relbias_k<<<(HH*SS*SS + 255)/256, 256>>>(rel_table, rp_bucket);
    gemm_k<true,true><<<dim3(4,4,HH),256>>>(ppq,DD,0,HDIM, ppk,DD,0,HDIM,
                                            pbias,SS,0,(long)SS*SS,
                                            SS,SS,HDIM, HH, 1.0f, nullptr);

    // ---- embedding gather (fp32) ----
    gather_k<<<(int)(((long)BB*SS*DD + 255)/256), 256>>>(tokens, embed);

    const long wS  = (long)NQKV * DD;
    const long woS = (long)DD * DD;

    for (int l = 0; l < NL; l++) {
        // quantize activation x -> limbs + row scales
        qact_k<<<BB*SS, 256>>>(px, px1, px0, psx);

        // fused QKV projection (int8): [8192,2304], emits bf16 hi/lo for attention
        gemm_i8<<<dim3(18,64), 256, GI_SMEM>>>(
            px1, px0, DD, psx,
            pw1 + l*wS, pw0 + l*wS, DD, pswq + l*NQKV,
            nullptr, pqkvh, pqkvl, NQKV, pbqkv + l*NQKV, DD);

        // fused scores + bias + softmax -> attn hi/lo (bf16 path)
        attn_sm_k<<<dim3(2, BB*HH), 256, AT_SMEM>>>(pqkvh, pqkvl, pqkvh + DD, pqkvl + DD,
                                                    pah, pal);

        // o[b,h] = attn_bh @ v_bh  (bf16 split, fp32 out)
        gemm_bf<<<dim3(1,1,BB*HH), 256, GM_SMEM>>>(
            pah, pal, SS, (long)HH*SS*SS, (long)SS*SS,
            pqkvh + 2*DD, pqkvl + 2*DD, NQKV, (long)SS*NQKV, HDIM,
            pof, DD, (long)SS*DD, HDIM,
            HDIM, SS, HH);

        // quantize o
        qact_k<<<BB*SS, 256>>>(pof, po1, po0, pso);

        // x = o @ Wo^T + bo  (int8, fp32 out)
        gemm_i8<<<dim3(6,64), 256, GI_SMEM>>>(
            po1, po0, DD, pso,
            pwo1 + l*woS, pwo0 + l*woS, DD, pswo + l*DD,
            px, nullptr, nullptr, DD, bo + l*DD, DD);
    }

    extract_k<<<(BB*DD + 255)/256, 256>>>(out);
}

// round 12
// speedup vs baseline: 2.6241x; 2.6241x over previous
#include <cuda_runtime.h>
#include <cuda_bf16.h>
#include <cstdint>
#include <math.h>

#define BB   32
#define SS   256
#define DD   768
#define HH   8
#define HDIM 96
#define NL   6
#define NQKV (3*DD)   // 2304

// ---------------- scratch (static device globals; no allocs allowed) ------
__device__ float g_bias[HH*SS*SS];
__device__ float g_w [SS*DD];
__device__ float g_pq[SS*DD];
__device__ float g_pk[SS*DD];

__device__ __nv_bfloat16 g_xh[BB*SS*DD], g_xl[BB*SS*DD];
__device__ __nv_bfloat16 g_qkvh[(long)BB*SS*NQKV], g_qkvl[(long)BB*SS*NQKV];
__device__ __nv_bfloat16 g_oh[BB*SS*DD], g_ol[BB*SS*DD];
__device__ __nv_bfloat16 g_ah[(long)BB*HH*SS*SS], g_al[(long)BB*HH*SS*SS];
__device__ __nv_bfloat16 g_wh[(long)NL*NQKV*DD], g_wl[(long)NL*NQKV*DD];
__device__ float         g_bqkv[NL*NQKV];
__device__ __nv_bfloat16 g_woh[NL*DD*DD], g_wol[NL*DD*DD];
// fused weights: Wf[l] = Wqkv[l+1] @ Wo[l]  (l = 0..4), and fused bias
__device__ __nv_bfloat16 g_wfh[(long)5*NQKV*DD], g_wfl[(long)5*NQKV*DD];
__device__ float         g_bf[5*NQKV];

// =====================  low-level helpers  =================================
__device__ __forceinline__ uint32_t smem_u32(const void* p) {
    uint32_t a;
    asm("{ .reg .u64 t; cvta.to.shared.u64 t, %1; cvt.u32.u64 %0, t; }" : "=r"(a) : "l"(p));
    return a;
}
__device__ __forceinline__ void cp16(uint32_t s, const void* g) {
    asm volatile("cp.async.cg.shared.global [%0], [%1], 16;" :: "r"(s), "l"(g));
}
__device__ __forceinline__ void cp16z(uint32_t s, const void* g, int ok) {
    int sz = ok ? 16 : 0;
    asm volatile("cp.async.cg.shared.global [%0], [%1], 16, %2;" :: "r"(s), "l"(g), "r"(sz));
}
__device__ __forceinline__ void cp_commit() { asm volatile("cp.async.commit_group;"); }

__device__ __forceinline__ void ldm4(uint32_t* r, uint32_t a) {
    asm volatile("ldmatrix.sync.aligned.m8n8.x4.shared.b16 {%0,%1,%2,%3}, [%4];"
        : "=r"(r[0]), "=r"(r[1]), "=r"(r[2]), "=r"(r[3]) : "r"(a));
}
__device__ __forceinline__ void ldm4t(uint32_t* r, uint32_t a) {
    asm volatile("ldmatrix.sync.aligned.m8n8.x4.trans.shared.b16 {%0,%1,%2,%3}, [%4];"
        : "=r"(r[0]), "=r"(r[1]), "=r"(r[2]), "=r"(r[3]) : "r"(a));
}
__device__ __forceinline__ void mma16816(float* d, const uint32_t* a, const uint32_t* b) {
    asm volatile(
        "mma.sync.aligned.m16n8k16.row.col.f32.bf16.bf16.f32 "
        "{%0,%1,%2,%3}, {%4,%5,%6,%7}, {%8,%9}, {%0,%1,%2,%3};"
        : "+f"(d[0]), "+f"(d[1]), "+f"(d[2]), "+f"(d[3])
        : "r"(a[0]), "r"(a[1]), "r"(a[2]), "r"(a[3]), "r"(b[0]), "r"(b[1]));
}

// =====================  tensor-core split-bf16 GEMM  =======================
// C = alpha * ((Ahi+Alo) @ op(Bhi+Blo) + bias)
// CTA tile 256x128, warp tile 64x64 (4m x 2n), BK=64, 2-stage pipeline (R9).
// BT=true : B stored [N,K] row-major -> ldmatrix non-trans
// BT=false: B stored [K,N] row-major -> ldmatrix trans
// stage layout: Ahi 0 (32KB), Alo 32768, Bhi 65536 (16KB), Blo 81920
#define GM_STAGE  98304
#define GM_SMEM   (2*GM_STAGE)   // 196608

template<bool BT>
__global__ void __launch_bounds__(256, 1)
gemm_mma(const __nv_bfloat16* __restrict__ Ah, const __nv_bfloat16* __restrict__ Al,
         int lda, long aO, long aI,
         const __nv_bfloat16* __restrict__ Bh, const __nv_bfloat16* __restrict__ Bl,
         int ldb, long bO, long bI,
         float* __restrict__ Cf, __nv_bfloat16* __restrict__ Ch, __nv_bfloat16* __restrict__ Cl,
         int ldc, long cO, long cI,
         int N, int K, int batchInner, float alpha, const float* __restrict__ bias)
{
    extern __shared__ char smem[];
    const uint32_t sb = smem_u32(smem);
    const int z  = blockIdx.z;
    const long zo = z / batchInner, zi = z % batchInner;
    Ah += zo * aO + zi * aI;  Al += zo * aO + zi * aI;
    Bh += zo * bO + zi * bI;  Bl += zo * bO + zi * bI;
    const long coff = zo * cO + zi * cI;

    const int m0 = blockIdx.y * 256;
    const int n0 = blockIdx.x * 128;
    const int tid = threadIdx.x, lane = tid & 31, wid = tid >> 5;
    const int wm = wid & 3, wn = wid >> 2;

    const __nv_bfloat16* gAh = Ah + (long)m0 * lda;
    const __nv_bfloat16* gAl = Al + (long)m0 * lda;
    const __nv_bfloat16* gBh = BT ? (Bh + (long)n0 * ldb) : (Bh + n0);
    const __nv_bfloat16* gBl = BT ? (Bl + (long)n0 * ldb) : (Bl + n0);

    float acc[4][8][4] = {};

    auto loads = [&](int kb, int st) {
        uint32_t s = sb + st * GM_STAGE;
        long ko = (long)kb * 64;
        #pragma unroll
        for (int e = 0; e < 8; e++) {        // A: 256 rows x 8 chunks (hi+lo)
            int idx = tid + e * 256;
            int r = idx >> 3, c = idx & 7;
            int cs = c ^ (r & 7);
            cp16(s +         r * 128 + cs * 16, gAh + (long)r * lda + ko + c * 8);
            cp16(s + 32768 + r * 128 + cs * 16, gAl + (long)r * lda + ko + c * 8);
        }
        if (BT) {
            #pragma unroll
            for (int e = 0; e < 4; e++) {    // B: 128 rows x 8 chunks
                int idx = tid + e * 256;
                int r = idx >> 3, c = idx & 7;
                int cs = c ^ (r & 7);
                cp16(s + 65536 + r * 128 + cs * 16, gBh + (long)r * ldb + ko + c * 8);
                cp16(s + 81920 + r * 128 + cs * 16, gBl + (long)r * ldb + ko + c * 8);
            }
        } else {
            #pragma unroll
            for (int e = 0; e < 4; e++) {    // B: 64 k-rows x 16 chunks
                int idx = tid + e * 256;
                int r = idx >> 4, c = idx & 15;
                int cs = c ^ (r & 7);
                int ok = (n0 + c * 8) < N;
                int co = ok ? c * 8 : 0;
                cp16z(s + 65536 + r * 256 + cs * 16, gBh + (ko + r) * (long)ldb + co, ok);
                cp16z(s + 81920 + r * 256 + cs * 16, gBl + (ko + r) * (long)ldb + co, ok);
            }
        }
        cp_commit();
    };

    auto comp = [&](int st) {
        uint32_t s = sb + st * GM_STAGE;
        #pragma unroll
        for (int kk = 0; kk < 4; kk++) {
            uint32_t ah[4][4], al[4][4], bh[8][2], bl[8][2];
            #pragma unroll
            for (int mf = 0; mf < 4; mf++) {
                int r = wm * 64 + mf * 16 + (lane & 15);
                int c = kk * 2 + (lane >> 4);
                int cs = c ^ (r & 7);
                ldm4(ah[mf], s +         r * 128 + cs * 16);
                ldm4(al[mf], s + 32768 + r * 128 + cs * 16);
            }
            if (BT) {
                #pragma unroll
                for (int np = 0; np < 4; np++) {
                    int r = wn * 64 + np * 16 + (lane & 7) + ((lane >> 4) & 1) * 8;
                    int c = kk * 2 + ((lane >> 3) & 1);
                    int cs = c ^ (r & 7);
                    uint32_t t[4];
                    ldm4(t, s + 65536 + r * 128 + cs * 16);
                    bh[2*np][0]=t[0]; bh[2*np][1]=t[1]; bh[2*np+1][0]=t[2]; bh[2*np+1][1]=t[3];
                    ldm4(t, s + 81920 + r * 128 + cs * 16);
                    bl[2*np][0]=t[0]; bl[2*np][1]=t[1]; bl[2*np+1][0]=t[2]; bl[2*np+1][1]=t[3];
                }
            } else {
                #pragma unroll
                for (int np = 0; np < 4; np++) {
                    int kr = kk * 16 + (lane & 15);
                    int nc = (wn * 64 + np * 16) / 8 + ((lane >> 4) & 1);
                    int cs = nc ^ (kr & 7);
                    uint32_t t[4];
                    ldm4t(t, s + 65536 + kr * 256 + cs * 16);
                    bh[2*np][0]=t[0]; bh[2*np][1]=t[1]; bh[2*np+1][0]=t[2]; bh[2*np+1][1]=t[3];
                    ldm4t(t, s + 81920 + kr * 256 + cs * 16);
                    bl[2*np][0]=t[0]; bl[2*np][1]=t[1]; bl[2*np+1][0]=t[2]; bl[2*np+1][1]=t[3];
                }
            }
            #pragma unroll
            for (int mf = 0; mf < 4; mf++)
                #pragma unroll
                for (int nf = 0; nf < 8; nf++) {
                    mma16816(acc[mf][nf], ah[mf], bh[nf]);
                    mma16816(acc[mf][nf], ah[mf], bl[nf]);
                    mma16816(acc[mf][nf], al[mf], bh[nf]);
                }
        }
    };

    const int nkb = K / 64;
    loads(0, 0);
    for (int kb = 0; kb < nkb; kb++) {
        if (kb + 1 < nkb) {
            loads(kb + 1, (kb + 1) & 1);
            asm volatile("cp.async.wait_group 1;");
        } else {
            asm volatile("cp.async.wait_group 0;");
        }
        __syncthreads();
        comp(kb & 1);
        __syncthreads();
    }

    // ---- epilogue ----
    #pragma unroll
    for (int mf = 0; mf < 4; mf++) {
        int rbase = m0 + wm * 64 + mf * 16 + (lane >> 2);
        #pragma unroll
        for (int nf = 0; nf < 8; nf++) {
            int col = n0 + wn * 64 + nf * 8 + (lane & 3) * 2;
            if (col >= N) continue;
            float bv0 = bias ? bias[col]     : 0.f;
            float bv1 = bias ? bias[col + 1] : 0.f;
            #pragma unroll
            for (int h = 0; h < 2; h++) {
                int rr = rbase + h * 8;
                float v0 = (acc[mf][nf][h * 2 + 0] + bv0) * alpha;
                float v1 = (acc[mf][nf][h * 2 + 1] + bv1) * alpha;
                long i0 = coff + (long)rr * ldc + col;
                if (Cf) { Cf[i0] = v0; Cf[i0 + 1] = v1; }
                if (Ch) {
                    __nv_bfloat16 h0 = __float2bfloat16(v0);
                    __nv_bfloat16 h1 = __float2bfloat16(v1);
                    *(__nv_bfloat162*)(Ch + i0) = __nv_bfloat162(h0, h1);
                    *(__nv_bfloat162*)(Cl + i0) = __nv_bfloat162(
                        __float2bfloat16(v0 - __bfloat162float(h0)),
                        __float2bfloat16(v1 - __bfloat162float(h1)));
                }
            }
        }
    }
}

// ========== fused scores + bias + softmax (emits attn hi/lo bf16) ==========
// Per CTA: 64 query rows x all 256 key cols for one (b,h). 8 warps span n.
#define AT_STAGE 40960
#define AT_SMEM  (3*AT_STAGE)   // 122880

__global__ void __launch_bounds__(256, 1)
attn_sm_k(const __nv_bfloat16* __restrict__ Qh, const __nv_bfloat16* __restrict__ Ql,
          const __nv_bfloat16* __restrict__ Kh, const __nv_bfloat16* __restrict__ Kl,
          __nv_bfloat16* __restrict__ Ph, __nv_bfloat16* __restrict__ Pl)
{
    extern __shared__ char smem[];
    __shared__ float s_red[64][8];
    const uint32_t sb = smem_u32(smem);
    const int z = blockIdx.y;              // b*HH + h
    const int b = z / HH, h = z % HH;
    const int m0 = blockIdx.x * 64;
    const int tid = threadIdx.x, lane = tid & 31, w = tid >> 5;

    const long off = (long)b * SS * NQKV + (long)h * HDIM;
    const __nv_bfloat16* gQh = Qh + off + (long)m0 * NQKV;
    const __nv_bfloat16* gQl = Ql + off + (long)m0 * NQKV;
    const __nv_bfloat16* gKh = Kh + off;
    const __nv_bfloat16* gKl = Kl + off;

    float acc[4][4][4] = {};

    auto loads = [&](int kb) {
        uint32_t s = sb + kb * AT_STAGE;
        long ko = (long)kb * 32;
        {   // Q: 64x32 hi/lo
            int r = tid >> 2, c = tid & 3;
            int cs = c ^ ((r >> 1) & 3);
            cp16(s +        r * 64 + cs * 16, gQh + (long)r * NQKV + ko + c * 8);
            cp16(s + 4096 + r * 64 + cs * 16, gQl + (long)r * NQKV + ko + c * 8);
        }
        #pragma unroll
        for (int e = 0; e < 4; e++) {      // K: 256x32 hi/lo
            int idx = tid + e * 256;
            int r = idx >> 2, c = idx & 3;
            int cs = c ^ ((r >> 1) & 3);
            cp16(s + 8192  + r * 64 + cs * 16, gKh + (long)r * NQKV + ko + c * 8);
            cp16(s + 24576 + r * 64 + cs * 16, gKl + (long)r * NQKV + ko + c * 8);
        }
        cp_commit();
    };

    loads(0); loads(1);
    for (int kb = 0; kb < 3; kb++) {
        if (kb < 2) asm volatile("cp.async.wait_group 1;");
        else        asm volatile("cp.async.wait_group 0;");
        __syncthreads();
        if (kb + 2 < 3) loads(kb + 2);
        uint32_t s = sb + kb * AT_STAGE;
        #pragma unroll
        for (int kk = 0; kk < 2; kk++) {
            uint32_t ah[4][4], al[4][4], bh[4][2], bl[4][2];
            #pragma unroll
            for (int mf = 0; mf < 4; mf++) {
                int r = mf * 16 + (lane & 15);
                int c = kk * 2 + (lane >> 4);
                int cs = c ^ ((r >> 1) & 3);
                ldm4(ah[mf], s +        r * 64 + cs * 16);
                ldm4(al[mf], s + 4096 + r * 64 + cs * 16);
            }
            #pragma unroll
            for (int np = 0; np < 2; np++) {
                int r = w * 32 + np * 16 + (lane & 7) + ((lane >> 4) & 1) * 8;
                int c = kk * 2 + ((lane >> 3) & 1);
                int cs = c ^ ((r >> 1) & 3);
                uint32_t t[4];
                ldm4(t, s + 8192 + r * 64 + cs * 16);
                bh[2*np][0]=t[0]; bh[2*np][1]=t[1]; bh[2*np+1][0]=t[2]; bh[2*np+1][1]=t[3];
                ldm4(t, s + 24576 + r * 64 + cs * 16);
                bl[2*np][0]=t[0]; bl[2*np][1]=t[1]; bl[2*np+1][0]=t[2]; bl[2*np+1][1]=t[3];
            }
            #pragma unroll
            for (int mf = 0; mf < 4; mf++)
                #pragma unroll
                for (int nf = 0; nf < 4; nf++) {
                    mma16816(acc[mf][nf], ah[mf], bh[nf]);
                    mma16816(acc[mf][nf], ah[mf], bl[nf]);
                    mma16816(acc[mf][nf], al[mf], bh[nf]);
                }
        }
    }

    // ---- bias add ----
    const float* bp = g_bias + (long)h * SS * SS;
    #pragma unroll
    for (int mf = 0; mf < 4; mf++)
        #pragma unroll
        for (int sub = 0; sub < 2; sub++) {
            int row = m0 + mf * 16 + (lane >> 2) + sub * 8;
            #pragma unroll
            for (int nf = 0; nf < 4; nf++) {
                int col = w * 32 + nf * 8 + (lane & 3) * 2;
                float2 bv = *(const float2*)(bp + (long)row * SS + col);
                acc[mf][nf][sub*2+0] += bv.x;
                acc[mf][nf][sub*2+1] += bv.y;
            }
        }

    // ---- row max ----
    float mx[4][2];
    #pragma unroll
    for (int mf = 0; mf < 4; mf++)
        #pragma unroll
        for (int sub = 0; sub < 2; sub++) {
            float m = -3.4e38f;
            #pragma unroll
            for (int nf = 0; nf < 4; nf++)
                m = fmaxf(m, fmaxf(acc[mf][nf][sub*2], acc[mf][nf][sub*2+1]));
            m = fmaxf(m, __shfl_xor_sync(0xffffffffu, m, 1));
            m = fmaxf(m, __shfl_xor_sync(0xffffffffu, m, 2));
            if ((lane & 3) == 0) s_red[mf*16 + (lane>>2) + sub*8][w] = m;
        }
    __syncthreads();
    #pragma unroll
    for (int mf = 0; mf < 4; mf++)
        #pragma unroll
        for (int sub = 0; sub < 2; sub++) {
            int r = mf*16 + (lane>>2) + sub*8;
            float m = s_red[r][0];
            #pragma unroll
            for (int ww = 1; ww < 8; ww++) m = fmaxf(m, s_red[r][ww]);
            mx[mf][sub] = m;
        }
    __syncthreads();

    // ---- exp + row sum ----
    float sm[4][2];
    #pragma unroll
    for (int mf = 0; mf < 4; mf++)
        #pragma unroll
        for (int sub = 0; sub < 2; sub++) {
            float ssum = 0.f;
            #pragma unroll
            for (int nf = 0; nf < 4; nf++) {
                float e0 = __expf(acc[mf][nf][sub*2+0] - mx[mf][sub]);
                float e1 = __expf(acc[mf][nf][sub*2+1] - mx[mf][sub]);
                acc[mf][nf][sub*2+0] = e0;
                acc[mf][nf][sub*2+1] = e1;
                ssum += e0 + e1;
            }
            ssum += __shfl_xor_sync(0xffffffffu, ssum, 1);
            ssum += __shfl_xor_sync(0xffffffffu, ssum, 2);
            if ((lane & 3) == 0) s_red[mf*16 + (lane>>2) + sub*8][w] = ssum;
        }
    __syncthreads();
    #pragma unroll
    for (int mf = 0; mf < 4; mf++)
        #pragma unroll
        for (int sub = 0; sub < 2; sub++) {
            int r = mf*16 + (lane>>2) + sub*8;
            float ssum = 0.f;
            #pragma unroll
            for (int ww = 0; ww < 8; ww++) ssum += s_red[r][ww];
            sm[mf][sub] = 1.f / ssum;
        }

    // ---- write attn hi/lo bf16 ----
    #pragma unroll
    for (int mf = 0; mf < 4; mf++)
        #pragma unroll
        for (int sub = 0; sub < 2; sub++) {
            int row = m0 + mf * 16 + (lane >> 2) + sub * 8;
            float r = sm[mf][sub];
            #pragma unroll
            for (int nf = 0; nf < 4; nf++) {
                int col = w * 32 + nf * 8 + (lane & 3) * 2;
                float p0 = acc[mf][nf][sub*2+0] * r;
                float p1 = acc[mf][nf][sub*2+1] * r;
                __nv_bfloat16 h0 = __float2bfloat16(p0);
                __nv_bfloat16 h1 = __float2bfloat16(p1);
                long idx = ((long)z * SS + row) * SS + col;
                *(__nv_bfloat162*)(Ph + idx) = __nv_bfloat162(h0, h1);
                *(__nv_bfloat162*)(Pl + idx) = __nv_bfloat162(
                    __float2bfloat16(p0 - __bfloat162float(h0)),
                    __float2bfloat16(p1 - __bfloat162float(h1)));
            }
        }
}

// ============ weight packing: QKV combined [NL][2304,768] hi/lo ============
__global__ void packqkv_k(const float* __restrict__ Wq, const float* __restrict__ Wk,
                          const float* __restrict__ Wv, float scale)
{
    long idx = (long)blockIdx.x * blockDim.x + threadIdx.x;
    if (idx >= (long)NL * NQKV * DD) return;
    int col = (int)(idx % DD);
    long t = idx / DD;
    int row = (int)(t % NQKV);
    int l = (int)(t / NQKV);
    const float* src; float sc = 1.f; int r = row;
    if (row < DD)            { src = Wq; sc = scale; }
    else if (row < 2*DD)     { src = Wk; r = row - DD; }
    else                     { src = Wv; r = row - 2*DD; }
    float v = src[((long)l * DD + r) * DD + col] * sc;
    __nv_bfloat16 h = __float2bfloat16(v);
    g_wh[idx] = h;
    g_wl[idx] = __float2bfloat16(v - __bfloat162float(h));
}
__global__ void packbias_k(const float* __restrict__ bq, const float* __restrict__ bk,
                           const float* __restrict__ bv, float scale)
{
    int idx = blockIdx.x * blockDim.x + threadIdx.x;
    if (idx >= NL * NQKV) return;
    int row = idx % NQKV, l = idx / NQKV;
    float v;
    if (row < DD)        v = bq[l*DD + row] * scale;
    else if (row < 2*DD) v = bk[l*DD + row - DD];
    else                 v = bv[l*DD + row - 2*DD];
    g_bqkv[idx] = v;
}

// fused bias: bf[l][j] = Wqkv_scaled[l+1][j,:] . bo[l] + bqkv_scaled[l+1][j]
__global__ void bfuse_k(const float* __restrict__ Wq, const float* __restrict__ Wk,
                        const float* __restrict__ Wv,
                        const float* __restrict__ bq, const float* __restrict__ bk,
                        const float* __restrict__ bv,
                        const float* __restrict__ bo, float scale)
{
    int gw = (blockIdx.x * blockDim.x + threadIdx.x) >> 5;
    int lane = threadIdx.x & 31;
    if (gw >= 5 * NQKV) return;
    int l = gw / NQKV, j = gw % NQKV;       // uses Wqkv(l+1), bo(l)
    const float* src; const float* bsrc; float fs = 1.f; int r = j;
    if (j < DD)        { src = Wq; bsrc = bq; fs = scale; }
    else if (j < 2*DD) { src = Wk; bsrc = bk; r = j - DD; }
    else               { src = Wv; bsrc = bv; r = j - 2*DD; }
    const float* wrow = src + ((long)(l + 1) * DD + r) * DD;
    const float* bor  = bo + (long)l * DD;
    float s = 0.f;
    for (int k = lane; k < DD; k += 32) s += wrow[k] * bor[k];
    #pragma unroll
    for (int o = 16; o > 0; o >>= 1) s += __shfl_xor_sync(0xffffffffu, s, o);
    if (lane == 0)
        g_bf[gw] = fs * (s + bsrc[(long)(l + 1) * DD + r]);
}

// =====================  fp32 -> bf16 hi/lo split (Wo) ======================
__global__ void split_k(const float* __restrict__ src,
                        __nv_bfloat16* __restrict__ hi,
                        __nv_bfloat16* __restrict__ lo, long n)
{
    long i = ((long)blockIdx.x * blockDim.x + threadIdx.x) * 4;
    if (i >= n) return;
    float4 v = *(const float4*)(src + i);
    __nv_bfloat16 h0 = __float2bfloat16(v.x), h1 = __float2bfloat16(v.y);
    __nv_bfloat16 h2 = __float2bfloat16(v.z), h3 = __float2bfloat16(v.w);
    *(__nv_bfloat162*)(hi + i)     = __nv_bfloat162(h0, h1);
    *(__nv_bfloat162*)(hi + i + 2) = __nv_bfloat162(h2, h3);
    *(__nv_bfloat162*)(lo + i)     = __nv_bfloat162(
        __float2bfloat16(v.x - __bfloat162float(h0)),
        __float2bfloat16(v.y - __bfloat162float(h1)));
    *(__nv_bfloat162*)(lo + i + 2) = __nv_bfloat162(
        __float2bfloat16(v.z - __bfloat162float(h2)),
        __float2bfloat16(v.w - __bfloat162float(h3)));
}

// ---------------- block reductions ----------------------------------------
__device__ __forceinline__ float blockReduceSum(float v, float* red) {
    #pragma unroll
    for (int o = 16; o > 0; o >>= 1) v += __shfl_xor_sync(0xffffffffu, v, o);
    int w = threadIdx.x >> 5;
    if ((threadIdx.x & 31) == 0) red[w] = v;
    __syncthreads();
    if (threadIdx.x < 32) {
        float t = (threadIdx.x < (blockDim.x >> 5)) ? red[threadIdx.x] : 0.f;
        #pragma unroll
        for (int o = 16; o > 0; o >>= 1) t += __shfl_xor_sync(0xffffffffu, t, o);
        if (threadIdx.x == 0) red[0] = t;
    }
    __syncthreads();
    float r = red[0];
    __syncthreads();
    return r;
}

// ---------------- fp32 SGEMM (tiny positional-bias path only) -------------
template<bool BT, bool ACCUM>
__global__ void __launch_bounds__(256)
gemm_k(const float* __restrict__ A, int lda, long aO, long aI,
       const float* __restrict__ B, int ldb, long bO, long bI,
       float* __restrict__ C, int ldc, long cO, long cI,
       int M, int N, int K, int batchInner,
       float alpha, const float* __restrict__ biasVec)
{
    __shared__ float As[16][65];
    __shared__ float Bs[16][65];
    int z = blockIdx.z;
    A += (long)(z / batchInner) * aO + (long)(z % batchInner) * aI;
    B += (long)(z / batchInner) * bO + (long)(z % batchInner) * bI;
    C += (long)(z / batchInner) * cO + (long)(z % batchInner) * cI;
    const int m0 = blockIdx.y * 64, n0 = blockIdx.x * 64;
    const int tid = threadIdx.x, tx = tid & 15, ty = tid >> 4;
    float acc[4][4] = {};
    for (int k0 = 0; k0 < K; k0 += 16) {
        #pragma unroll
        for (int e = 0; e < 4; e++) {
            int i = tid + e * 256;
            int m = i >> 4, kk = i & 15;
            float val = 0.f;
            if (m0 + m < M && k0 + kk < K) val = A[(long)(m0 + m) * lda + (k0 + kk)];
            As[kk][m] = val;
        }
        #pragma unroll
        for (int e = 0; e < 4; e++) {
            int i = tid + e * 256;
            float val = 0.f;
            if (BT) {
                int n = i >> 4, kk = i & 15;
                if (n0 + n < N && k0 + kk < K) val = B[(long)(n0 + n) * ldb + (k0 + kk)];
                Bs[kk][n] = val;
            } else {
                int kk = i >> 6, n = i & 63;
                if (n0 + n < N && k0 + kk < K) val = B[(long)(k0 + kk) * ldb + (n0 + n)];
                Bs[kk][n] = val;
            }
        }
        __syncthreads();
        #pragma unroll
        for (int kk = 0; kk < 16; kk++) {
            float ra[4], rb[4];
            #pragma unroll
            for (int i = 0; i < 4; i++) ra[i] = As[kk][ty * 4 + i];
            #pragma unroll
            for (int j = 0; j < 4; j++) rb[j] = Bs[kk][tx * 4 + j];
            #pragma unroll
            for (int i = 0; i < 4; i++)
                #pragma unroll
                for (int j = 0; j < 4; j++)
                    acc[i][j] = fmaf(ra[i], rb[j], acc[i][j]);
        }
        __syncthreads();
    }
    #pragma unroll
    for (int i = 0; i < 4; i++) {
        int m = m0 + ty * 4 + i;
        if (m >= M) continue;
        #pragma unroll
        for (int j = 0; j < 4; j++) {
            int n = n0 + tx * 4 + j;
            if (n >= N) continue;
            float v = acc[i][j];
            if (biasVec) v += biasVec[n];
            v *= alpha;
            long idx = (long)m * ldc + n;
            if (ACCUM) C[idx] += v; else C[idx] = v;
        }
    }
}

// ---------------- layernorm of pos_emb rows -------------------------------
__global__ void ln_k(const float* __restrict__ x, const float* __restrict__ g,
                     const float* __restrict__ b)
{
    __shared__ float red[32];
    int row = blockIdx.x;
    const float* xr = x + (long)row * DD;
    int tid = threadIdx.x;
    float v[3];
    float s = 0.f;
    #pragma unroll
    for (int e = 0; e < 3; e++) { v[e] = xr[tid + e * 256]; s += v[e]; }
    float mu = blockReduceSum(s, red) * (1.0f / DD);
    float s2 = 0.f;
    #pragma unroll
    for (int e = 0; e < 3; e++) { float d = v[e] - mu; s2 += d * d; }
    float var = blockReduceSum(s2, red) * (1.0f / DD);
    float inv = rsqrtf(var + 1e-5f);
    #pragma unroll
    for (int e = 0; e < 3; e++) {
        int c = tid + e * 256;
        g_w[(long)row * DD + c] = (v[e] - mu) * inv * g[c] + b[c];
    }
}

// ---------------- relative bias init ---------------------------------------
__global__ void relbias_k(const float* __restrict__ table, const int* __restrict__ bucket)
{
    long idx = (long)blockIdx.x * blockDim.x + threadIdx.x;
    if (idx >= (long)HH * SS * SS) return;
    int j = idx % SS;
    long t = idx / SS;
    int i = t % SS;
    int h = t / SS;
    g_bias[idx] = table[bucket[i * SS + j] * HH + h];
}

// ---------------- embedding gather (hi/lo split only) ----------------------
__global__ void gather_k(const int* __restrict__ tok, const float* __restrict__ emb)
{
    long idx = (long)blockIdx.x * blockDim.x + threadIdx.x;
    if (idx >= (long)BB * SS * DD) return;
    int d = idx % DD;
    long bs = idx / DD;
    float v = emb[(long)tok[bs] * DD + d];
    __nv_bfloat16 h = __float2bfloat16(v);
    g_xh[idx] = h;
    g_xl[idx] = __float2bfloat16(v - __bfloat162float(h));
}

// -------- final: out[b,n] = o[b,0,:] . Wo5[n,:] + bo5[n]  (32x768 GEMV) ----
__global__ void final_k(const float* __restrict__ Wo5, const float* __restrict__ bo5,
                        float* __restrict__ out)
{
    int gw = (blockIdx.x * blockDim.x + threadIdx.x) >> 5;
    int lane = threadIdx.x & 31;
    if (gw >= BB * DD) return;
    int b = gw / DD, n = gw % DD;
    const long ob = (long)b * SS * DD;       // row s=0 of batch b
    const float* wr = Wo5 + (long)n * DD;
    float s = 0.f;
    for (int k = lane; k < DD; k += 32)
        s += (__bfloat162float(g_oh[ob + k]) + __bfloat162float(g_ol[ob + k])) * wr[k];
    #pragma unroll
    for (int o = 16; o > 0; o >>= 1) s += __shfl_xor_sync(0xffffffffu, s, o);
    if (lane == 0) out[gw] = s + bo5[n];
}

// ---------------------------------------------------------------------------
extern "C" void kernel_launch(void* const* d_in, const int* in_sizes, int n_in,
                              void* d_out, int out_size)
{
    const int*   tokens    = (const int*)  d_in[0];
    const float* embed     = (const float*)d_in[1];
    const float* pos_emb   = (const float*)d_in[2];
    const float* pos_q_w   = (const float*)d_in[3];
    const float* pos_q_b   = (const float*)d_in[4];
    const float* pos_k_w   = (const float*)d_in[5];
    const float* pos_k_b   = (const float*)d_in[6];
    const float* pos_ln_g  = (const float*)d_in[7];
    const float* pos_ln_b  = (const float*)d_in[8];
    const float* rel_table = (const float*)d_in[9];
    const int*   rp_bucket = (const int*)  d_in[10];
    const float* Wq = (const float*)d_in[11];
    const float* bq = (const float*)d_in[12];
    const float* Wk = (const float*)d_in[13];
    const float* bk = (const float*)d_in[14];
    const float* Wv = (const float*)d_in[15];
    const float* bv = (const float*)d_in[16];
    const float* Wo = (const float*)d_in[17];
    const float* bo = (const float*)d_in[18];
    float* out = (float*)d_out;

    float *pbias, *pw, *ppq, *ppk, *pbqkv, *pbf;
    cudaGetSymbolAddress((void**)&pbias,g_bias);
    cudaGetSymbolAddress((void**)&pw,   g_w);
    cudaGetSymbolAddress((void**)&ppq,  g_pq);
    cudaGetSymbolAddress((void**)&ppk,  g_pk);
    cudaGetSymbolAddress((void**)&pbqkv,g_bqkv);
    cudaGetSymbolAddress((void**)&pbf,  g_bf);

    __nv_bfloat16 *pxh,*pxl,*pqkvh,*pqkvl,*poh,*pol,*pah,*pal;
    __nv_bfloat16 *pwh,*pwl,*pwoh,*pwol,*pwfh,*pwfl;
    cudaGetSymbolAddress((void**)&pxh, g_xh);     cudaGetSymbolAddress((void**)&pxl, g_xl);
    cudaGetSymbolAddress((void**)&pqkvh, g_qkvh); cudaGetSymbolAddress((void**)&pqkvl, g_qkvl);
    cudaGetSymbolAddress((void**)&poh, g_oh);     cudaGetSymbolAddress((void**)&pol, g_ol);
    cudaGetSymbolAddress((void**)&pah, g_ah);     cudaGetSymbolAddress((void**)&pal, g_al);
    cudaGetSymbolAddress((void**)&pwh, g_wh);     cudaGetSymbolAddress((void**)&pwl, g_wl);
    cudaGetSymbolAddress((void**)&pwoh, g_woh);   cudaGetSymbolAddress((void**)&pwol, g_wol);
    cudaGetSymbolAddress((void**)&pwfh, g_wfh);   cudaGetSymbolAddress((void**)&pwfl, g_wfl);

    cudaFuncSetAttribute(gemm_mma<true>,  cudaFuncAttributeMaxDynamicSharedMemorySize, GM_SMEM);
    cudaFuncSetAttribute(gemm_mma<false>, cudaFuncAttributeMaxDynamicSharedMemorySize, GM_SMEM);
    cudaFuncSetAttribute(attn_sm_k, cudaFuncAttributeMaxDynamicSharedMemorySize, AT_SMEM);

    const float scale = rsqrtf((float)(HDIM * 2));
    const long wS  = (long)NQKV * DD;
    const long woS = (long)DD * DD;

    // ---- weight packing: QKV hi/lo (scale folded into q), Wo hi/lo ----
    const long nWQKV = (long)NL * NQKV * DD;
    packqkv_k<<<(int)((nWQKV + 255)/256), 256>>>(Wq, Wk, Wv, scale);
    packbias_k<<<(NL*NQKV + 255)/256, 256>>>(bq, bk, bv, scale);
    const long nW = (long)NL * DD * DD;
    split_k<<<(int)((nW/4 + 255)/256), 256>>>(Wo, pwoh, pwol, nW);

    // ---- fused weights: Wf[l] = Wqkv[l+1] @ Wo[l]  (l = 0..4) ----
    // A = Wqkv(l+1) [2304,768] hi/lo; B = Wo(l) [768,768] in [K,N] layout.
    gemm_mma<false><<<dim3(6,9,5), 256, GM_SMEM>>>(
        pwh + wS, pwl + wS, DD, wS, 0,
        pwoh, pwol, DD, woS, 0,
        nullptr, pwfh, pwfl, DD, (long)NQKV*DD, 0,
        DD, DD, 1, 1.0f, nullptr);
    bfuse_k<<<(5*NQKV*32 + 255)/256, 256>>>(Wq, Wk, Wv, bq, bk, bv, bo, scale);

    // ---- positional bias (once; fp32 path) ----
    ln_k<<<SS, 256>>>(pos_emb, pos_ln_g, pos_ln_b);
    gemm_k<true,false><<<dim3(12,4,1),256>>>(pw,DD,0,0, pos_q_w,DD,0,0, ppq,DD,0,0,
                                             SS,DD,DD, 1, scale, pos_q_b);
    gemm_k<true,false><<<dim3(12,4,1),256>>>(pw,DD,0,0, pos_k_w,DD,0,0, ppk,DD,0,0,
                                             SS,DD,DD, 1, 1.0f, pos_k_b);
    relbias_k<<<(HH*SS*SS + 255)/256, 256>>>(rel_table, rp_bucket);
    gemm_k<true,true><<<dim3(4,4,HH),256>>>(ppq,DD,0,HDIM, ppk,DD,0,HDIM,
                                            pbias,SS,0,(long)SS*SS,
                                            SS,SS,HDIM, HH, 1.0f, nullptr);

    // ---- embedding gather (hi/lo) ----
    gather_k<<<(int)(((long)BB*SS*DD + 255)/256), 256>>>(tokens, embed);

    // ---- layer 0 QKV from embeddings ----
    gemm_mma<true><<<dim3(18,32,1),256,GM_SMEM>>>(
        pxh,pxl,DD,0,0, pwh,pwl,DD,0,0,
        nullptr,pqkvh,pqkvl, NQKV,0,0, NQKV, DD, 1, 1.0f, pbqkv);

    for (int l = 0; l < NL; l++) {
        // fused scores + bias + softmax -> attn hi/lo
        attn_sm_k<<<dim3(4, BB*HH), 256, AT_SMEM>>>(pqkvh, pqkvl, pqkvh + DD, pqkvl + DD,
                                                    pah, pal);

        // o[b,h] = attn_bh @ v_bh  (M=256 = one y-tile; B [K,N] -> trans ldmatrix)
        gemm_mma<false><<<dim3(1,1,BB*HH),256,GM_SMEM>>>(
            pah,pal,SS,(long)HH*SS*SS,(long)SS*SS,
            pqkvh+2*DD,pqkvl+2*DD,NQKV,(long)SS*NQKV,HDIM,
            nullptr,poh,pol, DD,(long)SS*DD,HDIM,
            HDIM, SS, HH, 1.0f, nullptr);

        if (l < NL - 1) {
            // fused out-proj + next QKV: qkv(l+1) = o @ Wf(l)^T + bf(l)
            gemm_mma<true><<<dim3(18,32,1),256,GM_SMEM>>>(
                poh,pol,DD,0,0, pwfh + (long)l*wS, pwfl + (long)l*wS, DD,0,0,
                nullptr,pqkvh,pqkvl, NQKV,0,0, NQKV, DD, 1, 1.0f, pbf + l*NQKV);
        }
    }

    // final: out = o[:,0,:] @ Wo5^T + bo5
    final_k<<<(BB*DD*32 + 255)/256, 256>>>(Wo + (long)(NL-1)*woS, bo + (long)(NL-1)*DD, out);
}